// round 16
// baseline (speedup 1.0000x reference)
#include <cuda_runtime.h>
#include <math.h>

#define HH 112
#define CC 32
#define W2 49
#define TOPK 4
#define KC 196
#define NW 256
#define HEADS 8
// 32^-0.5 * log2(e): softmax in log2 domain (no max subtraction; safe range)
#define SCALE_L2 0.25505654196908085f
// compensation for RZ-truncation bias of P and V operands in tf32 MMA
#define COMP 1.000650f

#define KP_OFF 0        // Kp: 200 rows * 32, fragment-ordered blocks, XOR-row swizzle
#define VS_OFF 6400     // Vsw: 200 rows * 32, XOR-col swizzle
#define SM_TOT 12800    // floats -> 51200 B (4 CTAs/SM)

__device__ __forceinline__ float ex2(float x) {
    float r; asm("ex2.approx.f32 %0, %1;" : "=f"(r) : "f"(x)); return r;
}
__device__ __forceinline__ unsigned f2tf(float x) {
    unsigned r; asm("cvt.rna.tf32.f32 %0, %1;" : "=r"(r) : "f"(x)); return r;
}
__device__ __forceinline__ float tfbits(float x) {
    return __uint_as_float(f2tf(x));
}
__device__ __forceinline__ void cp16(unsigned dst, const void* src) {
    asm volatile("cp.async.cg.shared.global [%0], [%1], 16;" :: "r"(dst), "l"(src));
}
// RNA-round a K scalar (as bits) to the tf32 grid
__device__ __forceinline__ unsigned krna(unsigned x) { return x + 0x1000u; }
// non-volatile: ptxas may pipeline LDS/SHFL/HMMA freely
__device__ __forceinline__ void mma_tf32(float* cc,
                                         unsigned a0, unsigned a1, unsigned a2, unsigned a3,
                                         unsigned b0, unsigned b1) {
    asm("mma.sync.aligned.m16n8k8.row.col.f32.tf32.tf32.f32 "
        "{%0,%1,%2,%3}, {%4,%5,%6,%7}, {%8,%9}, {%0,%1,%2,%3};"
        : "+f"(cc[0]), "+f"(cc[1]), "+f"(cc[2]), "+f"(cc[3])
        : "r"(a0), "r"(a1), "r"(a2), "r"(a3), "r"(b0), "r"(b1));
}

// C-fragment -> A-fragment via 2-stage butterfly (4 SHFL).
__device__ __forceinline__ void frag_from_C(const float* pv, int c,
                                            unsigned& A0, unsigned& A1,
                                            unsigned& A2, unsigned& A3) {
    const bool n0 = (c & 1), n1 = (c & 2);
    float t0 = n0 ? pv[0] : pv[1];
    float t1 = n0 ? pv[2] : pv[3];
    float r0 = __shfl_xor_sync(0xffffffffu, t0, 1);
    float r1 = __shfl_xor_sync(0xffffffffu, t1, 1);
    float w0 = n0 ? r0 : pv[0];
    float w1 = n0 ? pv[1] : r0;
    float w2 = n0 ? r1 : pv[2];
    float w3 = n0 ? pv[3] : r1;
    t0 = n1 ? w0 : w1;
    t1 = n1 ? w2 : w3;
    r0 = __shfl_xor_sync(0xffffffffu, t0, 2);
    r1 = __shfl_xor_sync(0xffffffffu, t1, 2);
    A0 = __float_as_uint(n1 ? r0 : w0);
    A1 = __float_as_uint(n1 ? r1 : w2);
    A2 = __float_as_uint(n1 ? w1 : r0);
    A3 = __float_as_uint(n1 ? w3 : r1);
}

__device__ __forceinline__ int row_off(int row, const int* __restrict__ idxp) {
    int tt = (row * 21401) >> 20;           // row / 49
    int p  = row - tt*W2;
    int ws = __ldg(idxp + tt);
    int p7 = (p * 9363) >> 16;              // p / 7
    int y = (ws >> 4)*7 + p7;
    int x = (ws & 15)*7 + (p - p7*7);
    return (y*HH + x)*CC;
}

// Score tiles [T0, T0+NT): S += sum(exp2(QK)), o += P@V. No max tracking.
// K fragments: logical-k relabeled -> two uint4 LDS per tile (see gather).
template<int T0, int NT, bool ODD, bool MASK, bool WAITV>
__device__ __forceinline__ void do_chunk(
    const float* __restrict__ Kp, const float* __restrict__ Vsw,
    const unsigned* qa, int lane, int g, int c,
    float o[4][4], float& S0, float& S1)
{
    float acc[NT][4];
    #pragma unroll
    for (int nt = 0; nt < NT; nt++) {
        int krow = (T0 + nt)*8 + g;
        const float* kr = Kp + krow*32;
        int base = (8*c) ^ ((krow & 7) << 2);
        uint4 kb0 = *(const uint4*)(kr + base);         // kt0: x,y  kt1: z,w
        uint4 kb1 = *(const uint4*)(kr + (base ^ 4));   // kt2: x,y  kt3: z,w
        acc[nt][0] = acc[nt][1] = acc[nt][2] = acc[nt][3] = 0.f;
        mma_tf32(acc[nt], qa[0],  qa[1],  qa[2],  qa[3],  krna(kb0.x), krna(kb0.y));
        mma_tf32(acc[nt], qa[4],  qa[5],  qa[6],  qa[7],  krna(kb0.z), krna(kb0.w));
        mma_tf32(acc[nt], qa[8],  qa[9],  qa[10], qa[11], krna(kb1.x), krna(kb1.y));
        mma_tf32(acc[nt], qa[12], qa[13], qa[14], qa[15], krna(kb1.z), krna(kb1.w));
    }
    if (MASK) {
        if (c >= 2) { acc[NT-1][0] = acc[NT-1][1] = acc[NT-1][2] = acc[NT-1][3] = -INFINITY; }
    }
    // P = exp2(S) directly, accumulate row sums
    float s0 = 0.f, s1 = 0.f;
    #pragma unroll
    for (int nt = 0; nt < NT; nt++) {
        acc[nt][0] = ex2(acc[nt][0]);
        acc[nt][1] = ex2(acc[nt][1]);
        acc[nt][2] = ex2(acc[nt][2]);
        acc[nt][3] = ex2(acc[nt][3]);
        s0 += acc[nt][0] + acc[nt][1];
        s1 += acc[nt][2] + acc[nt][3];
    }
    s0 += __shfl_xor_sync(0xffffffffu, s0, 1);
    s0 += __shfl_xor_sync(0xffffffffu, s0, 2);
    s1 += __shfl_xor_sync(0xffffffffu, s1, 1);
    s1 += __shfl_xor_sync(0xffffffffu, s1, 2);
    S0 += s0; S1 += s1;

    if (WAITV) {   // V cp.async group completed while QK ran
        asm volatile("cp.async.wait_group 0;" ::: "memory");
        __syncthreads();
    }

    // PV: B from col-swizzled row-major Vsw (scalar LDS, conflict-free)
    #pragma unroll
    for (int p2 = 0; p2 < NT/2; p2++) {
        unsigned A00, A01, A02, A03, A10, A11, A12, A13;
        frag_from_C(acc[2*p2],     c, A00, A01, A02, A03);
        frag_from_C(acc[2*p2 + 1], c, A10, A11, A12, A13);
        int ktp = T0/2 + p2;
        const float* rp = Vsw + (16*ktp + c)*32 + g;
        #pragma unroll
        for (int n4 = 0; n4 < 4; n4++) {
            int co = 8*(n4 ^ c);
            float b0 = rp[co];
            float b1 = rp[co + 128];
            float b2 = rp[co + 256];
            float b3 = rp[co + 384];
            mma_tf32(o[n4], A00, A01, A02, A03,
                     __float_as_uint(b0), __float_as_uint(b1));
            mma_tf32(o[n4], A10, A11, A12, A13,
                     __float_as_uint(b2), __float_as_uint(b3));
        }
    }
    if (ODD) {
        unsigned A0, A1, A2, A3;
        frag_from_C(acc[NT-1], c, A0, A1, A2, A3);
        const float* rp = Vsw + ((T0 + NT - 1)*8 + c)*32 + g;
        #pragma unroll
        for (int n4 = 0; n4 < 4; n4++) {
            int co = 8*(n4 ^ c);
            float b0 = rp[co];
            float b1 = rp[co + 128];
            mma_tf32(o[n4], A0, A1, A2, A3,
                     __float_as_uint(b0), __float_as_uint(b1));
        }
    }
}

__global__ __launch_bounds__(128, 4)
void wsa_kernel(const float* __restrict__ q, const float* __restrict__ k,
                const float* __restrict__ v, const int* __restrict__ indices,
                float* __restrict__ out)
{
    extern __shared__ float sm[];
    float* Kp  = sm + KP_OFF;
    float* Vsw = sm + VS_OFF;

    const int w = blockIdx.x;
    const int h = blockIdx.y;
    const int b = blockIdx.z;
    const int t = threadIdx.x;
    const int wy = w >> 4, wx = w & 15;

    const size_t base = ((size_t)(b*HEADS + h)) * (size_t)(HH*HH*CC);
    const float* qb = q + base;
    const float* kb = k + base;
    const float* vb = v + base;
    const int* idxp = indices + ((b*HEADS + h)*NW + w)*TOPK;

    const int lane = t & 31, warp = t >> 5;
    const int g = lane >> 2, c = lane & 3;
    const int r0 = warp*16 + g, r1 = r0 + 8;
    const bool w0v = (r0 < W2), w1v = (r1 < W2);

    const unsigned smem_u32 = (unsigned)__cvta_generic_to_shared(sm);
    const unsigned kp_u32 = smem_u32;
    const unsigned vs_u32 = smem_u32 + VS_OFF*4;

    // ---- 1) K gather via cp.async (group K): physical block j of each row is
    // stored at fragment-order block (2*(j&3)+(j>>2)) ^ (row&7) ----
    {
        int j = t & 7;
        int bfrag = 2*(j & 3) + (j >> 2);
        #pragma unroll
        for (int m = 0; m < 13; m++) {
            int i = t + 128*m;
            if (i < 1568) {
                int row = i >> 3;
                unsigned dst = kp_u32 + (row*32 + ((bfrag ^ (row & 7)) << 2))*4;
                cp16(dst, kb + row_off(row, idxp) + 4*j);
            }
        }
        asm volatile("cp.async.commit_group;");   // group: K
    }

    // ---- 2) Q stage in Vsw overlay (overlaps K flight), fragment-ordered ----
    unsigned qa[16];
    {
        float* Qst = Vsw + warp*576;            // 16 rows * 36
        int j = lane & 7;
        int mo = 8*(j & 3) + 4*(j >> 2);        // fragment-order base for block j
        #pragma unroll
        for (int a = 0; a < 4; a++) {
            int jr = 4*a + (lane >> 3);         // 0..15
            int p = warp*16 + jr;
            float4 qq = make_float4(0.f, 0.f, 0.f, 0.f);
            if (p < W2) {
                int p7 = (p * 9363) >> 16;
                int y = wy*7 + p7, x = wx*7 + (p - p7*7);
                qq = *(const float4*)(qb + (y*HH + x)*CC + 4*j);
            }
            *(float4*)(Qst + jr*36 + mo) = make_float4(
                tfbits(qq.x * SCALE_L2), tfbits(qq.y * SCALE_L2),
                tfbits(qq.z * SCALE_L2), tfbits(qq.w * SCALE_L2));
        }
        __syncwarp();
        uint4 q00 = *(const uint4*)(Qst + g*36     + 8*c);      // r0 kt0-1
        uint4 q01 = *(const uint4*)(Qst + g*36     + 8*c + 4);  // r0 kt2-3
        uint4 q10 = *(const uint4*)(Qst + (8+g)*36 + 8*c);      // r1 kt0-1
        uint4 q11 = *(const uint4*)(Qst + (8+g)*36 + 8*c + 4);  // r1 kt2-3
        qa[0]  = q00.x; qa[1]  = q10.x; qa[2]  = q00.y; qa[3]  = q10.y;
        qa[4]  = q00.z; qa[5]  = q10.z; qa[6]  = q00.w; qa[7]  = q10.w;
        qa[8]  = q01.x; qa[9]  = q11.x; qa[10] = q01.y; qa[11] = q11.y;
        qa[12] = q01.z; qa[13] = q11.z; qa[14] = q01.w; qa[15] = q11.w;
    }
    __syncthreads();   // all warps done with Q staging -> Vsw free for V

    // ---- 3) V pad zero + V gather via cp.async (group V) ----
    Vsw[196*32 + t] = 0.f;
    {
        int c4 = (t & 7) << 2;
        #pragma unroll
        for (int m = 0; m < 13; m++) {
            int i = t + 128*m;
            if (i < 1568) {
                int row = i >> 3;
                unsigned dst = vs_u32 + (row*32 + (c4 ^ ((row & 3) << 3)))*4;
                cp16(dst, vb + row_off(row, idxp) + c4);
            }
        }
        asm volatile("cp.async.commit_group;");   // group: V
    }
    asm volatile("cp.async.wait_group 1;" ::: "memory");   // K arrived
    __syncthreads();

    // ======== per-warp attention; V flight hides under chunk-1 QK ========
    float o[4][4] = {};
    float S0 = 0.f, S1 = 0.f;
    do_chunk<0, 12, false, false, true >(Kp, Vsw, qa, lane, g, c, o, S0, S1);
    do_chunk<12, 13, true,  true,  false>(Kp, Vsw, qa, lane, g, c, o, S0, S1);

    // ---- epilogue (truncation-bias compensation folded into normalization) ----
    {
        float i0 = COMP / S0;
        float i1 = COMP / S1;
        float* ob = out + ((size_t)b*(HH*HH))*256 + h*CC;
        int p70 = (r0 * 9363) >> 16;
        int p71 = (r1 * 9363) >> 16;
        int y0 = wy*7 + p70, x0 = wx*7 + (r0 - p70*7);
        int y1 = wy*7 + p71, x1 = wx*7 + (r1 - p71*7);
        float* ob0 = ob + (size_t)(y0*HH + x0)*256;
        float* ob1 = ob + (size_t)(y1*HH + x1)*256;
        #pragma unroll
        for (int n4 = 0; n4 < 4; n4++) {
            int colb = n4*8 + 2*c;
            if (w0v) *(float2*)(ob0 + colb) = make_float2(o[n4][0]*i0, o[n4][1]*i0);
            if (w1v) *(float2*)(ob1 + colb) = make_float2(o[n4][2]*i1, o[n4][3]*i1);
        }
    }
}

extern "C" void kernel_launch(void* const* d_in, const int* in_sizes, int n_in,
                              void* d_out, int out_size)
{
    const float* q   = (const float*)d_in[0];
    const float* k   = (const float*)d_in[1];
    const float* v   = (const float*)d_in[2];
    const int*   idx = (const int*)d_in[3];
    float* out = (float*)d_out;

    int smem = SM_TOT * (int)sizeof(float);   // 51200 B -> 4 CTAs/SM
    cudaFuncSetAttribute(wsa_kernel, cudaFuncAttributeMaxDynamicSharedMemorySize, smem);

    dim3 grid(NW, HEADS, 4);
    wsa_kernel<<<grid, 128, smem>>>(q, k, v, idx, out);
}

// round 17
// speedup vs baseline: 1.1232x; 1.1232x over previous
#include <cuda_runtime.h>
#include <math.h>

#define HH 112
#define CC 32
#define W2 49
#define TOPK 4
#define KC 196
#define NW 256
#define HEADS 8
// 32^-0.5 * log2(e): softmax in log2 domain (no max subtraction; safe range)
#define SCALE_L2 0.25505654196908085f
// compensation for RZ-truncation bias of P and V operands in tf32 MMA
#define COMP 1.000650f

#define KP_OFF 0        // Kp: 200 rows * 32, 16B-granular XOR row swizzle (6400 floats)
#define VS_OFF 6400     // Vsw: 200 rows * 32, XOR-col swizzle           (6400 floats)
#define SM_TOT 12800    // floats -> 51200 B (4 CTAs/SM)

__device__ __forceinline__ float ex2(float x) {
    float r; asm("ex2.approx.f32 %0, %1;" : "=f"(r) : "f"(x)); return r;
}
__device__ __forceinline__ unsigned f2tf(float x) {
    unsigned r; asm("cvt.rna.tf32.f32 %0, %1;" : "=r"(r) : "f"(x)); return r;
}
__device__ __forceinline__ float tfbits(float x) {
    return __uint_as_float(f2tf(x));
}
__device__ __forceinline__ void cp16(unsigned dst, const void* src) {
    asm volatile("cp.async.cg.shared.global [%0], [%1], 16;" :: "r"(dst), "l"(src));
}
// RNA-round a K scalar to the tf32 grid: +0x1000 carries into the kept bits
__device__ __forceinline__ unsigned krna(float x) {
    return __float_as_uint(x) + 0x1000u;
}
// non-volatile: ptxas may pipeline LDS/SHFL/HMMA freely
__device__ __forceinline__ void mma_tf32(float* cc,
                                         unsigned a0, unsigned a1, unsigned a2, unsigned a3,
                                         unsigned b0, unsigned b1) {
    asm("mma.sync.aligned.m16n8k8.row.col.f32.tf32.tf32.f32 "
        "{%0,%1,%2,%3}, {%4,%5,%6,%7}, {%8,%9}, {%0,%1,%2,%3};"
        : "+f"(cc[0]), "+f"(cc[1]), "+f"(cc[2]), "+f"(cc[3])
        : "r"(a0), "r"(a1), "r"(a2), "r"(a3), "r"(b0), "r"(b1));
}

// C-fragment -> A-fragment via 2-stage butterfly (4 SHFL).
__device__ __forceinline__ void frag_from_C(const float* pv, int c,
                                            unsigned& A0, unsigned& A1,
                                            unsigned& A2, unsigned& A3) {
    const bool n0 = (c & 1), n1 = (c & 2);
    float t0 = n0 ? pv[0] : pv[1];
    float t1 = n0 ? pv[2] : pv[3];
    float r0 = __shfl_xor_sync(0xffffffffu, t0, 1);
    float r1 = __shfl_xor_sync(0xffffffffu, t1, 1);
    float w0 = n0 ? r0 : pv[0];
    float w1 = n0 ? pv[1] : r0;
    float w2 = n0 ? r1 : pv[2];
    float w3 = n0 ? pv[3] : r1;
    t0 = n1 ? w0 : w1;
    t1 = n1 ? w2 : w3;
    r0 = __shfl_xor_sync(0xffffffffu, t0, 2);
    r1 = __shfl_xor_sync(0xffffffffu, t1, 2);
    A0 = __float_as_uint(n1 ? r0 : w0);
    A1 = __float_as_uint(n1 ? r1 : w2);
    A2 = __float_as_uint(n1 ? w1 : r0);
    A3 = __float_as_uint(n1 ? w3 : r1);
}

__device__ __forceinline__ int row_off(int row, const int* __restrict__ idxp) {
    int tt = (row * 21401) >> 20;           // row / 49
    int p  = row - tt*W2;
    int ws = __ldg(idxp + tt);
    int p7 = (p * 9363) >> 16;              // p / 7
    int y = (ws >> 4)*7 + p7;
    int x = (ws & 15)*7 + (p - p7*7);
    return (y*HH + x)*CC;
}

// Score tiles [T0, T0+NT): S += sum(exp2(QK)), o += P@V. No max tracking.
// QK K-fragment loads are software-pipelined one tile ahead.
template<int T0, int NT, bool ODD, bool MASK, bool WAITV>
__device__ __forceinline__ void do_chunk(
    const float* __restrict__ Kp, const float* __restrict__ Vsw,
    const unsigned* qa, int lane, int g, int c,
    float o[4][4], float& S0, float& S1)
{
    float acc[NT][4];
    {
        // prologue: fragment loads for tile 0
        int krow = T0*8 + g;
        const float* kr = Kp + krow*32 + c;
        int sw = (krow & 7) << 2;
        uint4 kb0 = *(const uint4*)((const float*)((size_t)kr & ~63ull) + ((8*c) ^ sw));
        (void)kb0;
        float k0 = kr[0 ^ sw],  k1 = kr[4 ^ sw];
        float k2 = kr[8 ^ sw],  k3 = kr[12 ^ sw];
        float k4 = kr[16 ^ sw], k5 = kr[20 ^ sw];
        float k6 = kr[24 ^ sw], k7 = kr[28 ^ sw];
        #pragma unroll
        for (int nt = 0; nt < NT; nt++) {
            float n0v=0.f,n1v=0.f,n2v=0.f,n3v=0.f,n4v=0.f,n5v=0.f,n6v=0.f,n7v=0.f;
            if (nt + 1 < NT) {   // prefetch next tile's fragments
                int krow2 = (T0 + nt + 1)*8 + g;
                const float* kr2 = Kp + krow2*32 + c;
                int sw2 = (krow2 & 7) << 2;
                n0v = kr2[0 ^ sw2];  n1v = kr2[4 ^ sw2];
                n2v = kr2[8 ^ sw2];  n3v = kr2[12 ^ sw2];
                n4v = kr2[16 ^ sw2]; n5v = kr2[20 ^ sw2];
                n6v = kr2[24 ^ sw2]; n7v = kr2[28 ^ sw2];
            }
            acc[nt][0] = acc[nt][1] = acc[nt][2] = acc[nt][3] = 0.f;
            mma_tf32(acc[nt], qa[0],  qa[1],  qa[2],  qa[3],  krna(k0), krna(k1));
            mma_tf32(acc[nt], qa[4],  qa[5],  qa[6],  qa[7],  krna(k2), krna(k3));
            mma_tf32(acc[nt], qa[8],  qa[9],  qa[10], qa[11], krna(k4), krna(k5));
            mma_tf32(acc[nt], qa[12], qa[13], qa[14], qa[15], krna(k6), krna(k7));
            k0 = n0v; k1 = n1v; k2 = n2v; k3 = n3v;
            k4 = n4v; k5 = n5v; k6 = n6v; k7 = n7v;
        }
    }
    if (MASK) {
        if (c >= 2) { acc[NT-1][0] = acc[NT-1][1] = acc[NT-1][2] = acc[NT-1][3] = -INFINITY; }
    }
    // P = exp2(S) directly, accumulate row sums
    float s0 = 0.f, s1 = 0.f;
    #pragma unroll
    for (int nt = 0; nt < NT; nt++) {
        acc[nt][0] = ex2(acc[nt][0]);
        acc[nt][1] = ex2(acc[nt][1]);
        acc[nt][2] = ex2(acc[nt][2]);
        acc[nt][3] = ex2(acc[nt][3]);
        s0 += acc[nt][0] + acc[nt][1];
        s1 += acc[nt][2] + acc[nt][3];
    }
    s0 += __shfl_xor_sync(0xffffffffu, s0, 1);
    s0 += __shfl_xor_sync(0xffffffffu, s0, 2);
    s1 += __shfl_xor_sync(0xffffffffu, s1, 1);
    s1 += __shfl_xor_sync(0xffffffffu, s1, 2);
    S0 += s0; S1 += s1;

    if (WAITV) {   // V cp.async group completed while QK ran
        asm volatile("cp.async.wait_group 0;" ::: "memory");
        __syncthreads();
    }

    // PV: B from col-swizzled row-major Vsw (scalar LDS, conflict-free)
    #pragma unroll
    for (int p2 = 0; p2 < NT/2; p2++) {
        unsigned A00, A01, A02, A03, A10, A11, A12, A13;
        frag_from_C(acc[2*p2],     c, A00, A01, A02, A03);
        frag_from_C(acc[2*p2 + 1], c, A10, A11, A12, A13);
        int ktp = T0/2 + p2;
        const float* rp = Vsw + (16*ktp + c)*32 + g;
        #pragma unroll
        for (int n4 = 0; n4 < 4; n4++) {
            int co = 8*(n4 ^ c);
            float b0 = rp[co];
            float b1 = rp[co + 128];
            float b2 = rp[co + 256];
            float b3 = rp[co + 384];
            mma_tf32(o[n4], A00, A01, A02, A03,
                     __float_as_uint(b0), __float_as_uint(b1));
            mma_tf32(o[n4], A10, A11, A12, A13,
                     __float_as_uint(b2), __float_as_uint(b3));
        }
    }
    if (ODD) {
        unsigned A0, A1, A2, A3;
        frag_from_C(acc[NT-1], c, A0, A1, A2, A3);
        const float* rp = Vsw + ((T0 + NT - 1)*8 + c)*32 + g;
        #pragma unroll
        for (int n4 = 0; n4 < 4; n4++) {
            int co = 8*(n4 ^ c);
            float b0 = rp[co];
            float b1 = rp[co + 128];
            mma_tf32(o[n4], A0, A1, A2, A3,
                     __float_as_uint(b0), __float_as_uint(b1));
        }
    }
}

__global__ __launch_bounds__(128, 4)
void wsa_kernel(const float* __restrict__ q, const float* __restrict__ k,
                const float* __restrict__ v, const int* __restrict__ indices,
                float* __restrict__ out)
{
    extern __shared__ float sm[];
    float* Kp  = sm + KP_OFF;
    float* Vsw = sm + VS_OFF;

    const int w = blockIdx.x;
    const int h = blockIdx.y;
    const int b = blockIdx.z;
    const int t = threadIdx.x;
    const int wy = w >> 4, wx = w & 15;

    const size_t base = ((size_t)(b*HEADS + h)) * (size_t)(HH*HH*CC);
    const float* qb = q + base;
    const float* kb = k + base;
    const float* vb = v + base;
    const int* idxp = indices + ((b*HEADS + h)*NW + w)*TOPK;

    const int lane = t & 31, warp = t >> 5;
    const int g = lane >> 2, c = lane & 3;
    const int r0 = warp*16 + g, r1 = r0 + 8;
    const bool w0v = (r0 < W2), w1v = (r1 < W2);

    const unsigned smem_u32 = (unsigned)__cvta_generic_to_shared(sm);
    const unsigned kp_u32 = smem_u32;
    const unsigned vs_u32 = smem_u32 + VS_OFF*4;

    // ---- 1) K gather via cp.async (group K) ----
    {
        int c4 = (t & 7) << 2;
        #pragma unroll
        for (int m = 0; m < 13; m++) {
            int i = t + 128*m;
            if (i < 1568) {
                int row = i >> 3;
                unsigned dst = kp_u32 + (row*32 + (c4 ^ ((row & 7) << 2)))*4;
                cp16(dst, kb + row_off(row, idxp) + c4);
            }
        }
        asm volatile("cp.async.commit_group;");   // group: K
    }

    // ---- 2) Q stage in Vsw overlay (overlaps K flight): float4 LDG -> tf32 STS ----
    unsigned qa[16];
    {
        float* Qst = Vsw + warp*576;            // 16 rows * 36
        #pragma unroll
        for (int a = 0; a < 4; a++) {
            int j = 4*a + (lane >> 3);          // 0..15
            int p = warp*16 + j;
            int c4g = lane & 7;
            float4 qq = make_float4(0.f, 0.f, 0.f, 0.f);
            if (p < W2) {
                int p7 = (p * 9363) >> 16;
                int y = wy*7 + p7, x = wx*7 + (p - p7*7);
                qq = *(const float4*)(qb + (y*HH + x)*CC + 4*c4g);
            }
            float* qd = Qst + j*36 + 4*c4g;
            qd[0] = tfbits(qq.x * SCALE_L2);
            qd[1] = tfbits(qq.y * SCALE_L2);
            qd[2] = tfbits(qq.z * SCALE_L2);
            qd[3] = tfbits(qq.w * SCALE_L2);
        }
        __syncwarp();
        #pragma unroll
        for (int kt = 0; kt < 4; kt++) {
            qa[kt*4+0] = __float_as_uint(Qst[g*36     + kt*8 + c]);
            qa[kt*4+1] = __float_as_uint(Qst[(8+g)*36 + kt*8 + c]);
            qa[kt*4+2] = __float_as_uint(Qst[g*36     + kt*8 + c + 4]);
            qa[kt*4+3] = __float_as_uint(Qst[(8+g)*36 + kt*8 + c + 4]);
        }
    }
    __syncthreads();   // all warps done with Q staging -> Vsw free for V

    // ---- 3) V pad zero + V gather via cp.async (group V) ----
    Vsw[196*32 + t] = 0.f;
    {
        int c4 = (t & 7) << 2;
        #pragma unroll
        for (int m = 0; m < 13; m++) {
            int i = t + 128*m;
            if (i < 1568) {
                int row = i >> 3;
                unsigned dst = vs_u32 + (row*32 + (c4 ^ ((row & 3) << 3)))*4;
                cp16(dst, vb + row_off(row, idxp) + c4);
            }
        }
        asm volatile("cp.async.commit_group;");   // group: V
    }
    asm volatile("cp.async.wait_group 1;" ::: "memory");   // K arrived
    __syncthreads();

    // ======== per-warp attention; V flight hides under chunk-1 QK ========
    float o[4][4] = {};
    float S0 = 0.f, S1 = 0.f;
    do_chunk<0, 12, false, false, true >(Kp, Vsw, qa, lane, g, c, o, S0, S1);
    do_chunk<12, 13, true,  true,  false>(Kp, Vsw, qa, lane, g, c, o, S0, S1);

    // ---- epilogue (truncation-bias compensation folded into normalization) ----
    {
        float i0 = COMP / S0;
        float i1 = COMP / S1;
        float* ob = out + ((size_t)b*(HH*HH))*256 + h*CC;
        int p70 = (r0 * 9363) >> 16;
        int p71 = (r1 * 9363) >> 16;
        int y0 = wy*7 + p70, x0 = wx*7 + (r0 - p70*7);
        int y1 = wy*7 + p71, x1 = wx*7 + (r1 - p71*7);
        float* ob0 = ob + (size_t)(y0*HH + x0)*256;
        float* ob1 = ob + (size_t)(y1*HH + x1)*256;
        #pragma unroll
        for (int n4 = 0; n4 < 4; n4++) {
            int colb = n4*8 + 2*c;
            if (w0v) *(float2*)(ob0 + colb) = make_float2(o[n4][0]*i0, o[n4][1]*i0);
            if (w1v) *(float2*)(ob1 + colb) = make_float2(o[n4][2]*i1, o[n4][3]*i1);
        }
    }
}

extern "C" void kernel_launch(void* const* d_in, const int* in_sizes, int n_in,
                              void* d_out, int out_size)
{
    const float* q   = (const float*)d_in[0];
    const float* k   = (const float*)d_in[1];
    const float* v   = (const float*)d_in[2];
    const int*   idx = (const int*)d_in[3];
    float* out = (float*)d_out;

    int smem = SM_TOT * (int)sizeof(float);   // 51200 B -> 4 CTAs/SM
    cudaFuncSetAttribute(wsa_kernel, cudaFuncAttributeMaxDynamicSharedMemorySize, smem);

    dim3 grid(NW, HEADS, 4);
    wsa_kernel<<<grid, 128, smem>>>(q, k, v, idx, out);
}